// round 11
// baseline (speedup 1.0000x reference)
#include <cuda_runtime.h>
#include <stdint.h>

// GridGCNNearNeighbors, R11: R10 scan core (fused float4{x,y,z,|p|^2}, no
// prefetch) + single-wave grid with static multi-centroid warps (tail
// variance averaging, no atomics).
//
// For each (b, s) centroid, emit the 32 smallest point indices with squared
// distance <= 0.2^2 (reference: mask -> sort ascending indices -> take 32 ==
// first-32 in-radius indices in index order), padding with the first hit.
//
// Inputs identified by element count (harness delivers int64 as int32):
//   pos        float32 [8, 8192, 3]  -> 196608 elements (unique)
//   centroids  int32   [8, 2048]     -> 16384 elements (unique)
// Output: float32 [8, 2048, 32] (indices stored as floats, exact <= 8192)

namespace {
constexpr int Bb = 8;
constexpr int Nn = 8192;
constexpr int Ss = 2048;
constexpr int Kk = 32;
constexpr float THR = 0.04f;  // (float)(0.2**2)
constexpr int TOTAL = Bb * Ss;
constexpr int NBLOCKS = 152 * 24;            // one full wave at 24 blocks/SM
constexpr int NWARPS = NBLOCKS * 2;          // 64-thr blocks -> 7296 warps
}

// Fused SoA plane: one float4 {x, y, z, |p|^2} per point (1 MB static scratch)
__device__ __align__(16) float4 g_p[Bb * Nn];

__global__ __launch_bounds__(256)
void soa_transpose_kernel(const float* __restrict__ pos) {
    const int i = blockIdx.x * blockDim.x + threadIdx.x;
    if (i >= Bb * Nn) return;
    const float* p = pos + (size_t)i * 3;
    const float x = p[0], y = p[1], z = p[2];
    g_p[i] = make_float4(x, y, z, x * x + y * y + z * z);
}

__global__ __launch_bounds__(64, 24)
void gridgcn_knn_kernel(const int* __restrict__ centroids,
                        float* __restrict__ out) {
    const int warp_gid = (blockIdx.x << 1) | (threadIdx.x >> 5);
    const int lane = threadIdx.x & 31;
    const unsigned below = (1u << lane) - 1u;
    const unsigned mybit = 1u << lane;

    // Static interleaved assignment: 2-3 centroids per warp, cost-averaged
    #pragma unroll 1
    for (int cid = warp_gid; cid < TOTAL; cid += NWARPS) {
        const int b = cid >> 11;              // / 2048
        const int c = centroids[cid] & (Nn - 1);
        const float4* __restrict__ pp = g_p + b * Nn;

        // Center coordinates (warp-uniform broadcast; same bits as original pos)
        const float4 cp = pp[c];
        const float cx = cp.x, cy = cp.y, cz = cp.z;
        // Same expansion form as reference: ||c||^2 + ||p||^2 - 2 c.p
        const float sc = cx * cx + cy * cy + cz * cz;

        float* __restrict__ o = out + (size_t)cid * Kk;

        int have = 0;
        int first_idx = Nn;

        #pragma unroll 1
        for (int base = 0; base < Nn; base += 128) {
            // Four independent coalesced LDG.128 (one per 32-point group)
            const float4 p0 = pp[base + lane];
            const float4 p1 = pp[base + 32 + lane];
            const float4 p2 = pp[base + 64 + lane];
            const float4 p3 = pp[base + 96 + lane];

            const float d20 = sc + p0.w - 2.0f * (cx * p0.x + cy * p0.y + cz * p0.z);
            const float d21 = sc + p1.w - 2.0f * (cx * p1.x + cy * p1.y + cz * p1.z);
            const float d22 = sc + p2.w - 2.0f * (cx * p2.x + cy * p2.y + cz * p2.z);
            const float d23 = sc + p3.w - 2.0f * (cx * p3.x + cy * p3.y + cz * p3.z);

            // m_k bit l  <->  point  base + 32*k + l
            const unsigned m0 = __ballot_sync(0xffffffffu, d20 <= THR);
            const unsigned m1 = __ballot_sync(0xffffffffu, d21 <= THR);
            const unsigned m2 = __ballot_sync(0xffffffffu, d22 <= THR);
            const unsigned m3 = __ballot_sync(0xffffffffu, d23 <= THR);

            if (m0 | m1 | m2 | m3) {
                if (have == 0) {
                    if (m0)      first_idx = base + __ffs(m0) - 1;
                    else if (m1) first_idx = base + 32 + __ffs(m1) - 1;
                    else if (m2) first_idx = base + 64 + __ffs(m2) - 1;
                    else         first_idx = base + 96 + __ffs(m3) - 1;
                }
                int cum = have;
                {
                    const int s = cum + __popc(m0 & below);
                    if ((m0 & mybit) && s < Kk) o[s] = (float)(base + lane);
                    cum += __popc(m0);
                }
                {
                    const int s = cum + __popc(m1 & below);
                    if ((m1 & mybit) && s < Kk) o[s] = (float)(base + 32 + lane);
                    cum += __popc(m1);
                }
                {
                    const int s = cum + __popc(m2 & below);
                    if ((m2 & mybit) && s < Kk) o[s] = (float)(base + 64 + lane);
                    cum += __popc(m2);
                }
                {
                    const int s = cum + __popc(m3 & below);
                    if ((m3 & mybit) && s < Kk) o[s] = (float)(base + 96 + lane);
                    cum += __popc(m3);
                }
                have = cum;
                if (have >= Kk) break;
            }
        }

        // Pad tail with group_first (warp-uniform value)
        const float fpad = (float)first_idx;
        for (int i = have + lane; i < Kk; i += 32) o[i] = fpad;
    }
}

extern "C" void kernel_launch(void* const* d_in, const int* in_sizes, int n_in,
                              void* d_out, int out_size) {
    (void)out_size;
    const float* pos = nullptr;
    const int* centroids = nullptr;
    for (int i = 0; i < n_in; i++) {
        if (in_sizes[i] == Bb * Nn * 3)      pos = (const float*)d_in[i];
        else if (in_sizes[i] == Bb * Ss)     centroids = (const int*)d_in[i];
    }
    float* out = (float*)d_out;

    soa_transpose_kernel<<<(Bb * Nn + 255) / 256, 256>>>(pos);

    // Exactly one wave: warps self-balance by walking interleaved centroids
    gridgcn_knn_kernel<<<NBLOCKS, 64>>>(centroids, out);
}

// round 12
// speedup vs baseline: 1.0871x; 1.0871x over previous
#include <cuda_runtime.h>
#include <stdint.h>

// GridGCNNearNeighbors, R12: R10 core (fused float4{x,y,z,|p|^2}, static
// 1-centroid-per-warp, 8192 blocks x 64thr) with 256-point tiles (8 groups,
// MLP 8, half the loop overhead).
//
// For each (b, s) centroid, emit the 32 smallest point indices with squared
// distance <= 0.2^2 (reference: mask -> sort ascending indices -> take 32 ==
// first-32 in-radius indices in index order), padding with the first hit.
//
// Inputs identified by element count (harness delivers int64 as int32):
//   pos        float32 [8, 8192, 3]  -> 196608 elements (unique)
//   centroids  int32   [8, 2048]     -> 16384 elements (unique)
// Output: float32 [8, 2048, 32] (indices stored as floats, exact <= 8192)

namespace {
constexpr int Bb = 8;
constexpr int Nn = 8192;
constexpr int Ss = 2048;
constexpr int Kk = 32;
constexpr float THR = 0.04f;  // (float)(0.2**2)
}

// Fused SoA plane: one float4 {x, y, z, |p|^2} per point (1 MB static scratch)
__device__ __align__(16) float4 g_p[Bb * Nn];

__global__ __launch_bounds__(256)
void soa_transpose_kernel(const float* __restrict__ pos) {
    const int i = blockIdx.x * blockDim.x + threadIdx.x;
    if (i >= Bb * Nn) return;
    const float* p = pos + (size_t)i * 3;
    const float x = p[0], y = p[1], z = p[2];
    g_p[i] = make_float4(x, y, z, x * x + y * y + z * z);
}

__global__ __launch_bounds__(64, 20)
void gridgcn_knn_kernel(const int* __restrict__ centroids,
                        float* __restrict__ out) {
    const int warp_id = (blockIdx.x << 1) | (threadIdx.x >> 5);
    const int lane = threadIdx.x & 31;
    if (warp_id >= Bb * Ss) return;

    const int b = warp_id >> 11;          // / 2048
    const int c = centroids[warp_id] & (Nn - 1);
    const float4* __restrict__ pp = g_p + b * Nn;

    // Center coordinates (warp-uniform broadcast; same bits as original pos)
    const float4 cp = pp[c];
    const float cx = cp.x, cy = cp.y, cz = cp.z;
    // Same expansion form as reference: ||c||^2 + ||p||^2 - 2 c.p
    const float sc = cx * cx + cy * cy + cz * cz;

    float* __restrict__ o = out + (size_t)warp_id * Kk;

    int have = 0;
    int first_idx = Nn;
    const unsigned below = (1u << lane) - 1u;
    const unsigned mybit = 1u << lane;

    #pragma unroll 1
    for (int base = 0; base < Nn; base += 256) {
        // Eight independent coalesced LDG.128 issued back-to-back (MLP 8)
        const float4 p0 = pp[base + lane];
        const float4 p1 = pp[base + 32 + lane];
        const float4 p2 = pp[base + 64 + lane];
        const float4 p3 = pp[base + 96 + lane];
        const float4 p4 = pp[base + 128 + lane];
        const float4 p5 = pp[base + 160 + lane];
        const float4 p6 = pp[base + 192 + lane];
        const float4 p7 = pp[base + 224 + lane];

        const float d20 = sc + p0.w - 2.0f * (cx * p0.x + cy * p0.y + cz * p0.z);
        const float d21 = sc + p1.w - 2.0f * (cx * p1.x + cy * p1.y + cz * p1.z);
        const float d22 = sc + p2.w - 2.0f * (cx * p2.x + cy * p2.y + cz * p2.z);
        const float d23 = sc + p3.w - 2.0f * (cx * p3.x + cy * p3.y + cz * p3.z);
        const float d24 = sc + p4.w - 2.0f * (cx * p4.x + cy * p4.y + cz * p4.z);
        const float d25 = sc + p5.w - 2.0f * (cx * p5.x + cy * p5.y + cz * p5.z);
        const float d26 = sc + p6.w - 2.0f * (cx * p6.x + cy * p6.y + cz * p6.z);
        const float d27 = sc + p7.w - 2.0f * (cx * p7.x + cy * p7.y + cz * p7.z);

        // m_k bit l  <->  point  base + 32*k + l
        const unsigned m0 = __ballot_sync(0xffffffffu, d20 <= THR);
        const unsigned m1 = __ballot_sync(0xffffffffu, d21 <= THR);
        const unsigned m2 = __ballot_sync(0xffffffffu, d22 <= THR);
        const unsigned m3 = __ballot_sync(0xffffffffu, d23 <= THR);
        const unsigned m4 = __ballot_sync(0xffffffffu, d24 <= THR);
        const unsigned m5 = __ballot_sync(0xffffffffu, d25 <= THR);
        const unsigned m6 = __ballot_sync(0xffffffffu, d26 <= THR);
        const unsigned m7 = __ballot_sync(0xffffffffu, d27 <= THR);

        if (m0 | m1 | m2 | m3 | m4 | m5 | m6 | m7) {
            if (have == 0) {
                if (m0)      first_idx = base + __ffs(m0) - 1;
                else if (m1) first_idx = base + 32 + __ffs(m1) - 1;
                else if (m2) first_idx = base + 64 + __ffs(m2) - 1;
                else if (m3) first_idx = base + 96 + __ffs(m3) - 1;
                else if (m4) first_idx = base + 128 + __ffs(m4) - 1;
                else if (m5) first_idx = base + 160 + __ffs(m5) - 1;
                else if (m6) first_idx = base + 192 + __ffs(m6) - 1;
                else         first_idx = base + 224 + __ffs(m7) - 1;
            }
            int cum = have;
            const unsigned ms[8] = {m0, m1, m2, m3, m4, m5, m6, m7};
            #pragma unroll
            for (int k = 0; k < 8; k++) {
                const int s = cum + __popc(ms[k] & below);
                if ((ms[k] & mybit) && s < Kk) o[s] = (float)(base + 32 * k + lane);
                cum += __popc(ms[k]);
            }
            have = cum;
            if (have >= Kk) break;
        }
    }

    // Pad tail with group_first (warp-uniform value)
    const float fpad = (float)first_idx;
    for (int i = have + lane; i < Kk; i += 32) o[i] = fpad;
}

extern "C" void kernel_launch(void* const* d_in, const int* in_sizes, int n_in,
                              void* d_out, int out_size) {
    (void)out_size;
    const float* pos = nullptr;
    const int* centroids = nullptr;
    for (int i = 0; i < n_in; i++) {
        if (in_sizes[i] == Bb * Nn * 3)      pos = (const float*)d_in[i];
        else if (in_sizes[i] == Bb * Ss)     centroids = (const int*)d_in[i];
    }
    float* out = (float*)d_out;

    soa_transpose_kernel<<<(Bb * Nn + 255) / 256, 256>>>(pos);

    const int total_warps = Bb * Ss;           // 16384
    const int threads = 64;                    // 2 warps/block (R10 shape)
    const int blocks = total_warps / 2;        // 8192
    gridgcn_knn_kernel<<<blocks, threads>>>(centroids, out);
}